// round 8
// baseline (speedup 1.0000x reference)
#include <cuda_runtime.h>
#include <cuda_fp16.h>
#include <stdint.h>

#define QIN   90
#define QOUT  60
#define OPAD  64
#define KMAX  16
#define CINV  32
#define COUTV 32
#define H1V   32
#define H2V   64
#define DMAXV 1.0f
#define MAXB  4
#define ROWF  (QIN * CINV)     // 2880 floats per (b,n) row
#define NRB   8                // rows per iteration
#define NTH   512
#define FROWB (QIN * 128)      // 11520 B per n-row in f16 buffer (dup copies)
#define FB_BYTES (2 * NRB * FROWB)          // 184320
#define AG_FLOATS (NRB * 32 * CINV)         // 8192
#define WF_FLOATS (CINV * COUTV)            // 1024
#define SMEM_BYTES (FB_BYTES + (AG_FLOATS + WF_FLOATS) * 4)   // 221184

typedef unsigned long long ull;
// packed f32x2 FMA: acc = a*b + acc (elementwise on two packed floats)
#define FFMA2(acc, a, b) \
    asm("fma.rn.f32x2 %0, %1, %2, %0;" : "+l"(acc) : "l"(a), "l"(b))

// Per-(b,o) compacted tables produced by prep_kernel.
__device__ float          g_Mw[MAXB * OPAD * KMAX * CINV];  // [b][o][k][c], masked weights
__device__ unsigned short g_selo[MAXB * OPAD * KMAX];       // [b][o][k], BYTE offset i*128

// ---------------------------------------------------------------------------
// Kernel 1: distances + top-K selection + WeightNet MLP -> compact tables
// ---------------------------------------------------------------------------
__global__ void prep_kernel(const float* __restrict__ ang_in, const float* __restrict__ ang_out,
                            const float* __restrict__ W1, const float* __restrict__ b1,
                            const float* __restrict__ W2, const float* __restrict__ b2,
                            const float* __restrict__ W3, const float* __restrict__ b3,
                            int B)
{
    int bo = blockIdx.x;
    int b = bo / OPAD, o = bo % OPAD;
    int tid = threadIdx.x;

    if (o >= QOUT) {  // padded o slots: zero weights so main kernel adds nothing
        for (int i = tid; i < KMAX * CINV; i += blockDim.x)
            g_Mw[(b * OPAD + o) * KMAX * CINV + i] = 0.f;
        if (tid < KMAX) g_selo[(b * OPAD + o) * KMAX + tid] = 0;
        return;
    }

    __shared__ float sd[QIN], sbd[QIN];
    __shared__ int   ssel[KMAX];
    __shared__ float smask[KMAX], skd[KMAX], skbd[KMAX];
    __shared__ float sW2[H1V * H2V], sW3[H2V * CINV];
    __shared__ float sW1a[H1V], sW1b[H1V], sb1[H1V], sb2[H2V], sb3[CINV];
    __shared__ float sh1[KMAX][H1V], sh2[KMAX][H2V];

    for (int i = tid; i < H1V * H2V; i += 128) sW2[i] = W2[i];
    for (int i = tid; i < H2V * CINV; i += 128) sW3[i] = W3[i];
    if (tid < H2V) sb2[tid] = b2[tid];
    if (tid < CINV) sb3[tid] = b3[tid];
    if (tid < H1V) { sW1a[tid] = W1[3 * H1V + tid]; sW1b[tid] = W1[4 * H1V + tid]; sb1[tid] = b1[tid]; }

    float aox = ang_out[(b * QOUT + o) * 3 + 0];
    float aoy = ang_out[(b * QOUT + o) * 3 + 1];
    float aoz = ang_out[(b * QOUT + o) * 3 + 2];
    float nout = sqrtf(aox * aox + aoy * aoy + aoz * aoz);
    float ivo = (nout > 0.f) ? 1.f / nout : 0.f;
    float uox = aox * ivo, uoy = aoy * ivo, uoz = aoz * ivo;

    if (tid < QIN) {
        float x = ang_in[(b * QIN + tid) * 3 + 0];
        float y = ang_in[(b * QIN + tid) * 3 + 1];
        float z = ang_in[(b * QIN + tid) * 3 + 2];
        float nin = sqrtf(x * x + y * y + z * z);
        float ivi = (nin > 0.f) ? 1.f / nin : 0.f;
        float dot = (x * ivi) * uox + (y * ivi) * uoy + (z * ivi) * uoz;
        float d = acosf(fminf(fabsf(dot), 1.0f - 1e-7f));
        sd[tid] = d;
        sbd[tid] = nout - nin;
    }
    __syncthreads();

    if (tid < QIN) {
        float dt = sd[tid];
        int r = 0;
        for (int j = 0; j < QIN; j++) {
            float dj = sd[j];
            r += (dj < dt || (dj == dt && j < tid)) ? 1 : 0;
        }
        if (r < KMAX) {
            ssel[r] = tid;
            smask[r] = (dt <= DMAXV) ? 1.f : 0.f;
            skd[r] = dt;
            skbd[r] = sbd[tid];
        }
    }
    __syncthreads();

    int k = tid >> 3, ln = tid & 7;
    {
        float d = skd[k], bd = skbd[k];
        #pragma unroll
        for (int jj = 0; jj < 4; jj++) {
            int j = ln * 4 + jj;
            float h = fmaf(d, sW1a[j], fmaf(bd, sW1b[j], sb1[j]));
            sh1[k][j] = fmaxf(h, 0.f);
        }
    }
    __syncthreads();
    #pragma unroll
    for (int ll = 0; ll < 8; ll++) {
        int l = ln * 8 + ll;
        float acc = sb2[l];
        #pragma unroll 8
        for (int j = 0; j < H1V; j++) acc = fmaf(sh1[k][j], sW2[j * H2V + l], acc);
        sh2[k][l] = fmaxf(acc, 0.f);
    }
    __syncthreads();
    float m = smask[k];
    #pragma unroll
    for (int cc = 0; cc < 4; cc++) {
        int c = ln * 4 + cc;
        float acc = sb3[c];
        #pragma unroll 8
        for (int l = 0; l < H2V; l++) acc = fmaf(sh2[k][l], sW3[l * CINV + c], acc);
        g_Mw[((b * OPAD + o) * KMAX + k) * CINV + c] = m * acc;
    }
    if (ln == 0) g_selo[(b * OPAD + o) * KMAX + k] = (unsigned short)(ssel[k] * 128);
}

// ---------------------------------------------------------------------------
// Kernel 2: persistent gather-conv + Wf epilogue, fp16 f-cache.
//   1 CTA/SM (512 thr, 16 warps), gridDim.y = 2 o-halves.
//   Warp covers 2 o's: half-warp ho = one o, lane hl = channel PAIR.
//   f rows stored in smem as fp16, each 64B row DUPLICATED into a 128B slot:
//   half 0 reads copy at +0 (banks 0-15), half 1 at +64 (banks 16-31)
//   -> every gather LDS.32 is exactly one conflict-free 128B wavefront.
// ---------------------------------------------------------------------------
__device__ __forceinline__ void l2_prefetch_rows(const float* __restrict__ src,
                                                 int nr, int tid)
{
    int lines = nr * QIN;   // 128B lines per batch (90 per row)
    #pragma unroll
    for (int j = 0; j < 2; j++) {
        int l = tid + j * NTH;
        if (l < lines)
            asm volatile("prefetch.global.L2 [%0];" :: "l"(src + l * 32));
    }
}

// LDG fp32 -> cvt fp16 -> STS both copies. ho interleaves which copy is written
// first so each STS.64 instruction spans banks 0-31 at worst 2-way conflict.
__device__ __forceinline__ void stage_rows(const float* __restrict__ src, char* dst,
                                           int nr, int tid, int ho)
{
    for (int r = 0; r < nr; r++) {
        const float4* srow = (const float4*)(src + r * ROWF);
        char* drow = dst + r * FROWB;
        #pragma unroll
        for (int j = 0; j < 2; j++) {
            int u = tid + j * NTH;
            if (u < ROWF / 4) {               // 720 float4 units per row
                float4 v = srow[u];
                __half2 a = __floats2half2_rn(v.x, v.y);
                __half2 b = __floats2half2_rn(v.z, v.w);
                uint32_t ha = *(uint32_t*)&a, hb = *(uint32_t*)&b;
                ull hh = ((ull)hb << 32) | (ull)ha;
                int i = u >> 3, q = u & 7;    // i-row, float4-within-row
                char* pA = drow + i * 128 + q * 8;
                *(ull*)(pA + (ho ? 64 : 0)) = hh;
                *(ull*)(pA + (ho ? 0 : 64)) = hh;
            }
        }
    }
}

// Phase 1: gather-reduce, full NRB rows (stale tail rows guarded at store).
__device__ __forceinline__ void phase1(const char* __restrict__ fbc, float* __restrict__ aggs,
                                       const ull (&Mp)[16], const uint32_t (&ip)[8],
                                       int ogl, int ho, int hl)
{
    ull acc[NRB];
    #pragma unroll
    for (int r = 0; r < NRB; r++) acc[r] = 0ULL;

    const char* lanebase = fbc + ho * 64 + hl * 4;
    #pragma unroll
    for (int k = 0; k < 16; k++) {
        int off = (int)((ip[k >> 1] >> ((k & 1) * 16)) & 0xFFFFu);
        const char* p = lanebase + off;
        ull m = Mp[k];
        #pragma unroll
        for (int r = 0; r < NRB; r++) {
            uint32_t hv = *(const uint32_t*)(p + r * FROWB);   // LDS.32, 1 wf
            float2 fv = __half22float2(*(__half2*)&hv);
            ull fp; asm("mov.b64 %0, {%1, %2};" : "=l"(fp) : "f"(fv.x), "f"(fv.y));
            FFMA2(acc[r], m, fp);
        }
    }
    #pragma unroll
    for (int r = 0; r < NRB; r++)
        *(ull*)(aggs + (r * 32 + ogl) * CINV + 2 * hl) = acc[r];   // STS.64
}

__global__ void __launch_bounds__(NTH, 1)
conv_kernel(const float* __restrict__ f_in, const float* __restrict__ Wf,
            const float* __restrict__ bias_out, float* __restrict__ out,
            int B, int N)
{
    extern __shared__ char smem[];
    char*  fbuf = smem;                                   // [2][NRB * FROWB] fp16 dup
    float* aggs = (float*)(smem + FB_BYTES);              // [NRB][32][CINV]
    float* sWf  = aggs + AG_FLOATS;                       // [CINV][COUTV]

    const int tid   = threadIdx.x;
    const int lane  = tid & 31;
    const int warp  = tid >> 5;          // 0..15
    const int ho    = lane >> 4;         // which o of the warp's pair
    const int hl    = lane & 15;         // channel-pair index (c = 2hl, 2hl+1)
    const int obase = blockIdx.y * 32;   // this block's o-half
    const int ogl   = warp * 2 + ho;     // local o 0..31

    for (int i = tid; i < WF_FLOATS; i += NTH) sWf[i] = Wf[i];
    const float2 bias2 = ((const float2*)bias_out)[hl];

    long long R = (long long)B * N;
    long long chunk = (R + gridDim.x - 1) / gridDim.x;
    long long r0 = (long long)blockIdx.x * chunk;
    long long r1 = r0 + chunk; if (r1 > R) r1 = R;
    if (r0 >= r1) return;

    ull      Mp[16];
    uint32_t ip[8];

    long long g = r0;
    while (g < r1) {
        int b = (int)(g / N);
        long long gend = (long long)(b + 1) * N; if (gend > r1) gend = r1;

        // Per-batch tables: weights as native float2 pairs, u16 byte offsets.
        {
            int og = obase + ogl;
            const ull* mp = (const ull*)(g_Mw + (size_t)(b * OPAD + og) * KMAX * CINV);
            #pragma unroll
            for (int k = 0; k < 16; k++) Mp[k] = mp[k * (CINV / 2) + hl];
            const uint32_t* q = (const uint32_t*)&g_selo[(b * OPAD + og) * KMAX];
            #pragma unroll
            for (int j = 0; j < 8; j++) ip[j] = q[j];
        }

        // Prime: stage first batch, prefetch second into L2.
        {
            long long nb = gend - g;
            stage_rows(f_in + g * ROWF, fbuf, (int)(nb < NRB ? nb : NRB), tid, ho);
            if (nb > NRB) {
                long long n2 = nb - NRB;
                l2_prefetch_rows(f_in + (g + NRB) * ROWF, (int)(n2 < NRB ? n2 : NRB), tid);
            }
        }
        __syncthreads();

        int pb = 0;
        for (long long t = g; t < gend; t += NRB, pb ^= 1) {
            // L2 prefetch for batch t+2*NRB (consumed by stage next iteration).
            long long tp = t + 2 * NRB;
            if (tp < gend) {
                long long np = gend - tp;
                l2_prefetch_rows(f_in + tp * ROWF, (int)(np < NRB ? np : NRB), tid);
            }
            // Stage batch t+NRB (L2-hit LDG -> fp16 smem) into the other buffer.
            // Safe: its previous readers (phase1 of t-1) finished before the
            // barrier that ended iteration t-1.
            long long tn = t + NRB;
            if (tn < gend) {
                long long nn = gend - tn;
                stage_rows(f_in + tn * ROWF, fbuf + (pb ^ 1) * (NRB * FROWB),
                           (int)(nn < NRB ? nn : NRB), tid, ho);
            }

            const int nrows = (int)((gend - t) < NRB ? (gend - t) : NRB);

            phase1(fbuf + pb * (NRB * FROWB), aggs, Mp, ip, ogl, ho, hl);
            __syncwarp();      // aggs produced/consumed within the same half-warp

            // Phase 2: out[og, 2hl..2hl+1] = bias + sum_c' agg[og][c'] * Wf[c'][2hl..]
            float ax[NRB], ay[NRB];
            #pragma unroll
            for (int r = 0; r < NRB; r++) { ax[r] = bias2.x; ay[r] = bias2.y; }

            const float* arow = aggs + ogl * CINV;
            #pragma unroll
            for (int cq = 0; cq < 8; cq++) {
                float2 w0 = ((const float2*)(sWf + (cq * 4 + 0) * COUTV))[hl];
                float2 w1 = ((const float2*)(sWf + (cq * 4 + 1) * COUTV))[hl];
                float2 w2 = ((const float2*)(sWf + (cq * 4 + 2) * COUTV))[hl];
                float2 w3 = ((const float2*)(sWf + (cq * 4 + 3) * COUTV))[hl];
                #pragma unroll
                for (int r = 0; r < NRB; r++) {
                    float4 a4 = *(const float4*)(arow + r * (32 * CINV) + cq * 4);
                    ax[r] = fmaf(a4.x, w0.x, ax[r]);  ay[r] = fmaf(a4.x, w0.y, ay[r]);
                    ax[r] = fmaf(a4.y, w1.x, ax[r]);  ay[r] = fmaf(a4.y, w1.y, ay[r]);
                    ax[r] = fmaf(a4.z, w2.x, ax[r]);  ay[r] = fmaf(a4.z, w2.y, ay[r]);
                    ax[r] = fmaf(a4.w, w3.x, ax[r]);  ay[r] = fmaf(a4.w, w3.y, ay[r]);
                }
            }

            const int og = obase + ogl;
            if (og < QOUT) {
                #pragma unroll
                for (int r = 0; r < NRB; r++) {
                    if (r < nrows) {
                        float2 v; v.x = ax[r]; v.y = ay[r];
                        *(float2*)(out + (t + r) * (QOUT * COUTV) + og * COUTV + 2 * hl) = v;
                    }
                }
            }

            // All warps done reading fbuf[pb] and aggs; next iteration's stage
            // writes fbuf[pb] (for t+2*NRB) only after this barrier.
            __syncthreads();
        }
        g = gend;
    }
}

// ---------------------------------------------------------------------------
extern "C" void kernel_launch(void* const* d_in, const int* in_sizes, int n_in,
                              void* d_out, int out_size)
{
    const float* ang_in   = (const float*)d_in[0];
    const float* ang_out  = (const float*)d_in[1];
    const float* f_in     = (const float*)d_in[2];
    const float* W1       = (const float*)d_in[3];
    const float* b1       = (const float*)d_in[4];
    const float* W2       = (const float*)d_in[5];
    const float* b2       = (const float*)d_in[6];
    const float* W3       = (const float*)d_in[7];
    const float* b3       = (const float*)d_in[8];
    const float* Wf       = (const float*)d_in[9];
    const float* bias_out = (const float*)d_in[10];
    float* out = (float*)d_out;

    int B = in_sizes[0] / (QIN * 3);
    int N = in_sizes[2] / (B * QIN * CINV);

    cudaFuncSetAttribute(conv_kernel, cudaFuncAttributeMaxDynamicSharedMemorySize, SMEM_BYTES);

    prep_kernel<<<B * OPAD, 128>>>(ang_in, ang_out, W1, b1, W2, b2, W3, b3, B);

    int nsm = 148;
    cudaDeviceGetAttribute(&nsm, cudaDevAttrMultiProcessorCount, 0);
    int gx = nsm / 2; if (gx < 1) gx = 1;
    dim3 grid(gx, 2);
    conv_kernel<<<grid, NTH, SMEM_BYTES>>>(f_in, Wf, bias_out, out, B, N);
}

// round 10
// speedup vs baseline: 1.0412x; 1.0412x over previous
#include <cuda_runtime.h>
#include <stdint.h>

#define QIN   90
#define QOUT  60
#define OPAD  64
#define KMAX  16
#define CINV  32
#define COUTV 32
#define H1V   32
#define H2V   64
#define DMAXV 1.0f
#define MAXB  4
#define ROWF  (QIN * CINV)     // 2880 floats per (b,n) row
#define ROWB  (ROWF * 4)       // 11520 bytes per row
#define NRB   8                // rows per iteration
#define NTH   1024
#define FB_FLOATS (2 * NRB * ROWF)
#define AG_FLOATS (NRB * 32 * CINV)
#define WF_FLOATS (CINV * COUTV)
#define SMEM_BYTES ((FB_FLOATS + AG_FLOATS + WF_FLOATS) * 4)   // 221184

typedef unsigned long long ull;
// packed f32x2 FMA: acc = a*b + acc (elementwise on two packed floats)
#define FFMA2(acc, a, b) \
    asm("fma.rn.f32x2 %0, %1, %2, %0;" : "+l"(acc) : "l"(a), "l"(b))

// Per-(b,o) compacted tables produced by prep_kernel.
__device__ float          g_Mw[MAXB * OPAD * KMAX * CINV];  // [b][o][k][c], masked weights
__device__ unsigned short g_selo[MAXB * OPAD * KMAX];       // [b][o][k], BYTE offset i*128

// ---------------------------------------------------------------------------
// Kernel 1: distances + top-K selection + WeightNet MLP -> compact tables
// ---------------------------------------------------------------------------
__global__ void prep_kernel(const float* __restrict__ ang_in, const float* __restrict__ ang_out,
                            const float* __restrict__ W1, const float* __restrict__ b1,
                            const float* __restrict__ W2, const float* __restrict__ b2,
                            const float* __restrict__ W3, const float* __restrict__ b3,
                            int B)
{
    int bo = blockIdx.x;
    int b = bo / OPAD, o = bo % OPAD;
    int tid = threadIdx.x;

    if (o >= QOUT) {  // padded o slots: zero weights so main kernel adds nothing
        for (int i = tid; i < KMAX * CINV; i += blockDim.x)
            g_Mw[(b * OPAD + o) * KMAX * CINV + i] = 0.f;
        if (tid < KMAX) g_selo[(b * OPAD + o) * KMAX + tid] = 0;
        return;
    }

    __shared__ float sd[QIN], sbd[QIN];
    __shared__ int   ssel[KMAX];
    __shared__ float smask[KMAX], skd[KMAX], skbd[KMAX];
    __shared__ float sW2[H1V * H2V], sW3[H2V * CINV];
    __shared__ float sW1a[H1V], sW1b[H1V], sb1[H1V], sb2[H2V], sb3[CINV];
    __shared__ float sh1[KMAX][H1V], sh2[KMAX][H2V];

    for (int i = tid; i < H1V * H2V; i += 128) sW2[i] = W2[i];
    for (int i = tid; i < H2V * CINV; i += 128) sW3[i] = W3[i];
    if (tid < H2V) sb2[tid] = b2[tid];
    if (tid < CINV) sb3[tid] = b3[tid];
    if (tid < H1V) { sW1a[tid] = W1[3 * H1V + tid]; sW1b[tid] = W1[4 * H1V + tid]; sb1[tid] = b1[tid]; }

    float aox = ang_out[(b * QOUT + o) * 3 + 0];
    float aoy = ang_out[(b * QOUT + o) * 3 + 1];
    float aoz = ang_out[(b * QOUT + o) * 3 + 2];
    float nout = sqrtf(aox * aox + aoy * aoy + aoz * aoz);
    float ivo = (nout > 0.f) ? 1.f / nout : 0.f;
    float uox = aox * ivo, uoy = aoy * ivo, uoz = aoz * ivo;

    if (tid < QIN) {
        float x = ang_in[(b * QIN + tid) * 3 + 0];
        float y = ang_in[(b * QIN + tid) * 3 + 1];
        float z = ang_in[(b * QIN + tid) * 3 + 2];
        float nin = sqrtf(x * x + y * y + z * z);
        float ivi = (nin > 0.f) ? 1.f / nin : 0.f;
        float dot = (x * ivi) * uox + (y * ivi) * uoy + (z * ivi) * uoz;
        float d = acosf(fminf(fabsf(dot), 1.0f - 1e-7f));
        sd[tid] = d;
        sbd[tid] = nout - nin;
    }
    __syncthreads();

    if (tid < QIN) {
        float dt = sd[tid];
        int r = 0;
        for (int j = 0; j < QIN; j++) {
            float dj = sd[j];
            r += (dj < dt || (dj == dt && j < tid)) ? 1 : 0;
        }
        if (r < KMAX) {
            ssel[r] = tid;
            smask[r] = (dt <= DMAXV) ? 1.f : 0.f;
            skd[r] = dt;
            skbd[r] = sbd[tid];
        }
    }
    __syncthreads();

    int k = tid >> 3, ln = tid & 7;
    {
        float d = skd[k], bd = skbd[k];
        #pragma unroll
        for (int jj = 0; jj < 4; jj++) {
            int j = ln * 4 + jj;
            float h = fmaf(d, sW1a[j], fmaf(bd, sW1b[j], sb1[j]));
            sh1[k][j] = fmaxf(h, 0.f);
        }
    }
    __syncthreads();
    #pragma unroll
    for (int ll = 0; ll < 8; ll++) {
        int l = ln * 8 + ll;
        float acc = sb2[l];
        #pragma unroll 8
        for (int j = 0; j < H1V; j++) acc = fmaf(sh1[k][j], sW2[j * H2V + l], acc);
        sh2[k][l] = fmaxf(acc, 0.f);
    }
    __syncthreads();
    float m = smask[k];
    #pragma unroll
    for (int cc = 0; cc < 4; cc++) {
        int c = ln * 4 + cc;
        float acc = sb3[c];
        #pragma unroll 8
        for (int l = 0; l < H2V; l++) acc = fmaf(sh2[k][l], sW3[l * CINV + c], acc);
        g_Mw[((b * OPAD + o) * KMAX + k) * CINV + c] = m * acc;
    }
    if (ln == 0) g_selo[(b * OPAD + o) * KMAX + k] = (unsigned short)(ssel[k] * 128);
}

// ---------------------------------------------------------------------------
// Kernel 2: persistent gather-conv + Wf epilogue, fp32 f32x2 datapath.
//   1 CTA/SM, 1024 threads = 32 warps, gridDim.y = 2 o-halves.
//   Warp owns ONE o. Half-warp ho handles k of parity ho; lane hl = channel
//   pair (c = 2hl, 2hl+1). Partial sums merged with shfl_xor(16).
// ---------------------------------------------------------------------------
__device__ __forceinline__ void async_rows(float* dst, const float* __restrict__ src,
                                           int nr, int tid)
{
    uint32_t s = (uint32_t)__cvta_generic_to_shared(dst);
    int total = nr * (ROWF / 4);   // float4 count, up to 5760
    #pragma unroll
    for (int i = 0; i < 6; i++) {
        int idx = tid + i * NTH;
        if (idx < total)
            asm volatile("cp.async.cg.shared.global [%0], [%1], 16;\n"
                         :: "r"(s + idx * 16), "l"(src + idx * 4) : "memory");
    }
    asm volatile("cp.async.commit_group;\n" ::: "memory");
}

// Phase 1: gather-reduce, full NRB rows (stale tail rows guarded at store).
// Half-warp ho accumulates k = 2j+ho (j=0..7). Offset for k lives in u32 word
// j (= k>>1) at halfword ho (= k&1). Halves merged via shfl_xor(16); half ho
// stores rows ho*4..ho*4+3 to aggs.
__device__ __forceinline__ void phase1(const char* __restrict__ fbc, float* __restrict__ aggs,
                                       const ull (&Mp)[8], const uint32_t (&ip)[8],
                                       int ogl, int ho, int hl)
{
    ull acc[NRB];
    #pragma unroll
    for (int r = 0; r < NRB; r++) acc[r] = 0ULL;

    const char* lanebase = fbc + hl * 8;
    #pragma unroll
    for (int j = 0; j < 8; j++) {
        int off = (int)((ip[j] >> (ho * 16)) & 0xFFFFu);   // offset of k = 2j+ho
        const char* p = lanebase + off;
        ull m = Mp[j];
        #pragma unroll
        for (int r = 0; r < NRB; r++) {
            ull v = *(const ull*)(p + r * ROWB);   // LDS.64
            FFMA2(acc[r], m, v);
        }
    }
    // Merge even-k and odd-k halves; both halves end with the full sum.
    #pragma unroll
    for (int r = 0; r < NRB; r++) {
        float lo = __uint_as_float((uint32_t)acc[r]);
        float hi = __uint_as_float((uint32_t)(acc[r] >> 32));
        lo += __shfl_xor_sync(0xFFFFFFFFu, lo, 16);
        hi += __shfl_xor_sync(0xFFFFFFFFu, hi, 16);
        if ((r >> 2) == ho) {   // half 0 stores rows 0-3, half 1 rows 4-7
            float2 v; v.x = lo; v.y = hi;
            *(float2*)(aggs + (r * 32 + ogl) * CINV + 2 * hl) = v;   // STS.64
        }
    }
}

__global__ void __launch_bounds__(NTH, 1)
conv_kernel(const float* __restrict__ f_in, const float* __restrict__ Wf,
            const float* __restrict__ bias_out, float* __restrict__ out,
            int B, int N)
{
    extern __shared__ float smem[];
    float* fbuf = smem;                             // [2][NRB * ROWF]
    float* aggs = smem + FB_FLOATS;                 // [NRB][32][CINV]
    float* sWf  = smem + FB_FLOATS + AG_FLOATS;     // [CINV][COUTV]

    const int tid   = threadIdx.x;
    const int lane  = tid & 31;
    const int warp  = tid >> 5;          // 0..31
    const int ho    = lane >> 4;         // k-parity half / row-half
    const int hl    = lane & 15;         // channel-pair index (c = 2hl, 2hl+1)
    const int obase = blockIdx.y * 32;   // this block's o-half
    const int ogl   = warp;              // local o 0..31 (one o per warp)

    for (int i = tid; i < WF_FLOATS; i += NTH) sWf[i] = Wf[i];
    const float2 bias2 = ((const float2*)bias_out)[hl];

    long long R = (long long)B * N;
    long long chunk = (R + gridDim.x - 1) / gridDim.x;
    long long r0 = (long long)blockIdx.x * chunk;
    long long r1 = r0 + chunk; if (r1 > R) r1 = R;
    if (r0 >= r1) return;

    ull      Mp[8];
    uint32_t ip[8];

    long long g = r0;
    while (g < r1) {
        int b = (int)(g / N);
        long long gend = (long long)(b + 1) * N; if (gend > r1) gend = r1;

        // Per-batch tables: this half-warp's 8 k's (parity ho), c-pair hl,
        // and all 16 u16 offsets (8 u32 words).
        {
            int og = obase + ogl;
            const ull* mp = (const ull*)(g_Mw + (size_t)(b * OPAD + og) * KMAX * CINV);
            #pragma unroll
            for (int j = 0; j < 8; j++) Mp[j] = mp[(2 * j + ho) * (CINV / 2) + hl];
            const uint32_t* q = (const uint32_t*)&g_selo[(b * OPAD + og) * KMAX];
            #pragma unroll
            for (int j = 0; j < 8; j++) ip[j] = q[j];
        }

        {
            int nfirst = (int)((gend - g) < NRB ? (gend - g) : NRB);
            async_rows(fbuf, f_in + g * ROWF, nfirst, tid);
        }

        int pb = 0;
        for (long long t = g; t < gend; t += NRB, pb ^= 1) {
            long long tn = t + NRB;
            if (tn < gend) {
                int nr = (int)((gend - tn) < NRB ? (gend - tn) : NRB);
                async_rows(fbuf + (pb ^ 1) * (NRB * ROWF), f_in + tn * ROWF, nr, tid);
                asm volatile("cp.async.wait_group 1;\n" ::: "memory");
            } else {
                asm volatile("cp.async.wait_group 0;\n" ::: "memory");
            }
            __syncthreads();   // fbuf[pb] ready for all warps

            const int nrows = (int)((gend - t) < NRB ? (gend - t) : NRB);

            phase1((const char*)(fbuf + pb * (NRB * ROWF)), aggs, Mp, ip, ogl, ho, hl);

            // Block barrier: all warps done reading fbuf[pb] before anyone
            // loops around and prefetches into it next iteration.
            __syncthreads();

            // Phase 2: warp-private aggs -> out. Half ho handles rows ho*4..ho*4+3.
            float ax[4], ay[4];
            #pragma unroll
            for (int rr = 0; rr < 4; rr++) { ax[rr] = bias2.x; ay[rr] = bias2.y; }

            const float* arow = aggs + ogl * CINV;
            const int rb = ho * 4;
            #pragma unroll
            for (int cq = 0; cq < 8; cq++) {
                float2 w0 = ((const float2*)(sWf + (cq * 4 + 0) * COUTV))[hl];
                float2 w1 = ((const float2*)(sWf + (cq * 4 + 1) * COUTV))[hl];
                float2 w2 = ((const float2*)(sWf + (cq * 4 + 2) * COUTV))[hl];
                float2 w3 = ((const float2*)(sWf + (cq * 4 + 3) * COUTV))[hl];
                #pragma unroll
                for (int rr = 0; rr < 4; rr++) {
                    float4 a4 = *(const float4*)(arow + (rb + rr) * (32 * CINV) + cq * 4);
                    ax[rr] = fmaf(a4.x, w0.x, ax[rr]);  ay[rr] = fmaf(a4.x, w0.y, ay[rr]);
                    ax[rr] = fmaf(a4.y, w1.x, ax[rr]);  ay[rr] = fmaf(a4.y, w1.y, ay[rr]);
                    ax[rr] = fmaf(a4.z, w2.x, ax[rr]);  ay[rr] = fmaf(a4.z, w2.y, ay[rr]);
                    ax[rr] = fmaf(a4.w, w3.x, ax[rr]);  ay[rr] = fmaf(a4.w, w3.y, ay[rr]);
                }
            }

            const int og = obase + ogl;
            if (og < QOUT) {
                #pragma unroll
                for (int rr = 0; rr < 4; rr++) {
                    int r = rb + rr;
                    if (r < nrows) {
                        float2 v; v.x = ax[rr]; v.y = ay[rr];
                        *(float2*)(out + (t + r) * (QOUT * COUTV) + og * COUTV + 2 * hl) = v;
                    }
                }
            }
        }
        g = gend;
    }
}

// ---------------------------------------------------------------------------
extern "C" void kernel_launch(void* const* d_in, const int* in_sizes, int n_in,
                              void* d_out, int out_size)
{
    const float* ang_in   = (const float*)d_in[0];
    const float* ang_out  = (const float*)d_in[1];
    const float* f_in     = (const float*)d_in[2];
    const float* W1       = (const float*)d_in[3];
    const float* b1       = (const float*)d_in[4];
    const float* W2       = (const float*)d_in[5];
    const float* b2       = (const float*)d_in[6];
    const float* W3       = (const float*)d_in[7];
    const float* b3       = (const float*)d_in[8];
    const float* Wf       = (const float*)d_in[9];
    const float* bias_out = (const float*)d_in[10];
    float* out = (float*)d_out;

    int B = in_sizes[0] / (QIN * 3);
    int N = in_sizes[2] / (B * QIN * CINV);

    cudaFuncSetAttribute(conv_kernel, cudaFuncAttributeMaxDynamicSharedMemorySize, SMEM_BYTES);

    prep_kernel<<<B * OPAD, 128>>>(ang_in, ang_out, W1, b1, W2, b2, W3, b3, B);

    int nsm = 148;
    cudaDeviceGetAttribute(&nsm, cudaDevAttrMultiProcessorCount, 0);
    dim3 grid(nsm, 2);
    conv_kernel<<<grid, NTH, SMEM_BYTES>>>(f_in, Wf, bias_out, out, B, N);
}